// round 10
// baseline (speedup 1.0000x reference)
#include <cuda_runtime.h>
#include <cuda_bf16.h>
#include <cstdint>

#define T_LEN  2048
#define NBATCH 2
#define DMODEL 512
#define SWIN   32
#define MROWS  4096      // T_LEN * NBATCH
#define BDIM   1024      // NBATCH * DMODEL
#define NCHUNK 64        // T_LEN / 32

// bf16 hi/lo pool layout (element offsets)
#define IN_ELEMS   (MROWS * DMODEL)          // 2097152
#define W_ELEMS    (DMODEL * DMODEL)         // 262144
#define OFF_XQ     0
#define OFF_XK     (IN_ELEMS)
#define OFF_XV     (2 * IN_ELEMS)
#define OFF_WQ     (3 * IN_ELEMS)
#define OFF_WK     (3 * IN_ELEMS + W_ELEMS)
#define OFF_WV     (3 * IN_ELEMS + 2 * W_ELEMS)
#define OFF_WO     (3 * IN_ELEMS + 3 * W_ELEMS)
#define TOT_ELEMS  (3 * IN_ELEMS + 4 * W_ELEMS)   // 7340032
#define IN_F4      (IN_ELEMS / 4)
#define W_F4       (W_ELEMS / 4)
#define TOT_F4     (TOT_ELEMS / 4)                // 1835008

// ---------------- device scratch ----------------------------------------------
__device__ float  g_q  [MROWS * DMODEL];
__device__ float  g_k  [MROWS * DMODEL];
__device__ float  g_v  [MROWS * DMODEL];
__device__ __nv_bfloat16 g_hi[TOT_ELEMS];
__device__ __nv_bfloat16 g_lo[TOT_ELEMS];
__device__ __nv_bfloat16 g_yh[MROWS * DMODEL];
__device__ __nv_bfloat16 g_yl[MROWS * DMODEL];
__device__ float2 g_ekk[T_LEN * BDIM];          // (ek, ek*v) packed
__device__ float2 g_ps2[NCHUNK * BDIM];         // chunk partials -> exclusive prefix
__device__ float  g_colmax_part[32 * T_LEN];
__device__ float  g_pbmax[T_LEN];
__device__ float  g_ml_part[128 * DMODEL];
__device__ float  g_ml[DMODEL];
__device__ float2 g_expw2[T_LEN * SWIN];        // (w, w) duplicated weights

// ---------------- packed f32x2 helpers ----------------------------------------
__device__ __forceinline__ unsigned long long pack2(float lo, float hi) {
    unsigned long long r;
    asm("mov.b64 %0, {%1, %2};" : "=l"(r) : "f"(lo), "f"(hi));
    return r;
}
__device__ __forceinline__ void unpack2(unsigned long long v, float& lo, float& hi) {
    asm("mov.b64 {%0, %1}, %2;" : "=f"(lo), "=f"(hi) : "l"(v));
}
__device__ __forceinline__ unsigned long long ffma2(unsigned long long a,
                                                    unsigned long long b,
                                                    unsigned long long c) {
    unsigned long long d;
    asm("fma.rn.f32x2 %0, %1, %2, %3;" : "=l"(d) : "l"(a), "l"(b), "l"(c));
    return d;
}
__device__ __forceinline__ unsigned long long add2(unsigned long long a,
                                                   unsigned long long b) {
    unsigned long long d;
    asm("add.rn.f32x2 %0, %1, %2;" : "=l"(d) : "l"(a), "l"(b));
    return d;
}

// ================= bf16x3 split-precision warp-MMA GEMM ========================
#define LDT     40                       // bf16 elems per smem row (32 + 8 pad)
#define TILE_BYTES (128 * LDT * 2)       // 10240 B
#define STAGE_BYTES (4 * TILE_BYTES)     // Ah, Al, Bh, Bl = 40960 B
#define NSTAGE  3
#define SMEM_MMA (NSTAGE * STAGE_BYTES)  // 122880 B

__device__ __forceinline__ uint32_t smem_u32(const void* p) {
    uint32_t a;
    asm("{ .reg .u64 t; cvta.to.shared.u64 t, %1; cvt.u32.u64 %0, t; }"
        : "=r"(a) : "l"(p));
    return a;
}
__device__ __forceinline__ void cpa16(uint32_t dst, const void* src) {
    asm volatile("cp.async.ca.shared.global [%0], [%1], 16;"
                 :: "r"(dst), "l"(src));
}
#define CP_COMMIT() asm volatile("cp.async.commit_group;" ::: "memory")
#define CP_WAIT(n)  asm volatile("cp.async.wait_group %0;" :: "n"(n) : "memory")

__device__ __forceinline__ void ldsm4(uint32_t* r, uint32_t a) {
    asm volatile("ldmatrix.sync.aligned.m8n8.x4.shared.b16 {%0,%1,%2,%3}, [%4];"
                 : "=r"(r[0]), "=r"(r[1]), "=r"(r[2]), "=r"(r[3]) : "r"(a));
}
__device__ __forceinline__ void mma_bf16(float* c, const uint32_t* a, const uint32_t* b) {
    asm volatile(
        "mma.sync.aligned.m16n8k16.row.col.f32.bf16.bf16.f32 "
        "{%0,%1,%2,%3}, {%4,%5,%6,%7}, {%8,%9}, {%0,%1,%2,%3};"
        : "+f"(c[0]), "+f"(c[1]), "+f"(c[2]), "+f"(c[3])
        : "r"(a[0]), "r"(a[1]), "r"(a[2]), "r"(a[3]), "r"(b[0]), "r"(b[1]));
}

// A/B already split to bf16 hi/lo in gmem; mainloop = cp.async + ldmatrix + MMA.
__device__ __forceinline__ void gemm_mma_body(const __nv_bfloat16* __restrict__ Ah,
                                              const __nv_bfloat16* __restrict__ Al,
                                              const __nv_bfloat16* __restrict__ Bh,
                                              const __nv_bfloat16* __restrict__ Bl,
                                              const float* __restrict__ bias,
                                              float* __restrict__ out) {
    extern __shared__ char smem[];
    const int tid    = threadIdx.x;
    const int lane   = tid & 31;
    const int wid    = tid >> 5;
    const int warp_m = wid & 1;
    const int warp_n = wid >> 1;
    const int m0 = blockIdx.y * 128;
    const int n0 = blockIdx.x * 128;

    const uint32_t sbase = smem_u32(smem);
    const uint32_t a_off = ((warp_m * 64 + (lane & 15)) * LDT + ((lane >> 4) * 8)) * 2;
    const uint32_t b_off = ((warp_n * 32 + (lane & 7) + ((lane >> 4) & 1) * 8) * LDT
                            + (((lane >> 3) & 1) * 8)) * 2;

    const __nv_bfloat16* srcs[4] = {Ah + (size_t)m0 * 512, Al + (size_t)m0 * 512,
                                    Bh + (size_t)n0 * 512, Bl + (size_t)n0 * 512};

    float acc[4][4][4];
#pragma unroll
    for (int i = 0; i < 4; ++i)
#pragma unroll
        for (int j = 0; j < 4; ++j)
#pragma unroll
            for (int q = 0; q < 4; ++q) acc[i][j][q] = 0.0f;

    auto issue_stage = [&](int c) {
        const uint32_t sb = sbase + (c % NSTAGE) * STAGE_BYTES;
#pragma unroll
        for (int i = 0; i < 8; ++i) {
            int q   = i * 256 + tid;
            int tile = q >> 9;           // constant per unrolled i
            int s    = q & 511;
            int row  = s >> 2, ch = s & 3;
            const __nv_bfloat16* src = srcs[tile] + (size_t)row * 512 + c * 32 + ch * 8;
            cpa16(sb + tile * TILE_BYTES + row * (LDT * 2) + ch * 16, src);
        }
        CP_COMMIT();
    };

    issue_stage(0);
    issue_stage(1);

    for (int c = 0; c < 16; ++c) {
        if (c < 15) { CP_WAIT(1); } else { CP_WAIT(0); }
        __syncthreads();

        const uint32_t sa = sbase + (c % NSTAGE) * STAGE_BYTES;

#pragma unroll
        for (int kf = 0; kf < 2; ++kf) {
            const uint32_t kb = kf * 32;    // 16 bf16 = 32 bytes
            uint32_t bh4[2][4], bl4[2][4];
#pragma unroll
            for (int p = 0; p < 2; ++p) {
                uint32_t ba = sa + 2 * TILE_BYTES + b_off + p * (16 * LDT * 2) + kb;
                ldsm4(bh4[p], ba);
                ldsm4(bl4[p], ba + TILE_BYTES);
            }
#pragma unroll
            for (int mf = 0; mf < 4; ++mf) {
                uint32_t aa = sa + a_off + mf * (16 * LDT * 2) + kb;
                uint32_t ah[4], al[4];
                ldsm4(ah, aa);
                ldsm4(al, aa + TILE_BYTES);
#pragma unroll
                for (int nf = 0; nf < 4; ++nf) {
                    const uint32_t* bh = &bh4[nf >> 1][(nf & 1) * 2];
                    const uint32_t* bl = &bl4[nf >> 1][(nf & 1) * 2];
                    mma_bf16(acc[mf][nf], ah, bh);
                    mma_bf16(acc[mf][nf], ah, bl);
                    mma_bf16(acc[mf][nf], al, bh);
                }
            }
        }

        __syncthreads();                 // all warps done reading stage c
        if (c + 2 < 16) issue_stage(c + 2);
    }

    const int rbase = m0 + warp_m * 64 + (lane >> 2);
    const int cbase = n0 + warp_n * 32 + (lane & 3) * 2;
#pragma unroll
    for (int mf = 0; mf < 4; ++mf) {
#pragma unroll
        for (int nf = 0; nf < 4; ++nf) {
            int col = cbase + nf * 8;
            float b0 = bias[col], b1 = bias[col + 1];
            float* p0 = out + (size_t)(rbase + mf * 16) * 512 + col;
            float* p1 = p0 + 8 * 512;
            float2 v0 = {acc[mf][nf][0] + b0, acc[mf][nf][1] + b1};
            float2 v1 = {acc[mf][nf][2] + b0, acc[mf][nf][3] + b1};
            *(float2*)p0 = v0;
            *(float2*)p1 = v1;
        }
    }
}

__global__ void __launch_bounds__(256, 1)
gemm_qkv_kernel(const float* __restrict__ bq, const float* __restrict__ bk,
                const float* __restrict__ bv) {
    if (blockIdx.z == 0)
        gemm_mma_body(g_hi + OFF_XQ, g_lo + OFF_XQ, g_hi + OFF_WQ, g_lo + OFF_WQ, bq, g_q);
    else if (blockIdx.z == 1)
        gemm_mma_body(g_hi + OFF_XK, g_lo + OFF_XK, g_hi + OFF_WK, g_lo + OFF_WK, bk, g_k);
    else
        gemm_mma_body(g_hi + OFF_XV, g_lo + OFF_XV, g_hi + OFF_WV, g_lo + OFF_WV, bv, g_v);
}

__global__ void __launch_bounds__(256, 1)
gemm_o_kernel(const float* __restrict__ bo, float* __restrict__ out) {
    gemm_mma_body(g_yh, g_yl, g_hi + OFF_WO, g_lo + OFF_WO, bo, out);
}

// ---------------- fp32 -> bf16 hi/lo split, one pass over X(q,k,v) + W --------
__global__ void cvt_kernel(const float* __restrict__ xq, const float* __restrict__ xk,
                           const float* __restrict__ xv, const float* __restrict__ Wq,
                           const float* __restrict__ Wk, const float* __restrict__ Wv,
                           const float* __restrict__ Wo) {
    int idx = blockIdx.x * 256 + threadIdx.x;      // float4 index
    if (idx >= TOT_F4) return;
    const float* src;
    int local;
    if (idx < 3 * IN_F4) {
        int w = idx / IN_F4;
        src = (w == 0) ? xq : (w == 1) ? xk : xv;
        local = idx - w * IN_F4;
    } else {
        int r = idx - 3 * IN_F4;
        int w = r / W_F4;
        src = (w == 0) ? Wq : (w == 1) ? Wk : (w == 2) ? Wv : Wo;
        local = r - w * W_F4;
    }
    float4 v = ((const float4*)src)[local];
    __nv_bfloat16 h0 = __float2bfloat16_rn(v.x);
    __nv_bfloat16 h1 = __float2bfloat16_rn(v.y);
    __nv_bfloat16 h2 = __float2bfloat16_rn(v.z);
    __nv_bfloat16 h3 = __float2bfloat16_rn(v.w);
    __nv_bfloat162 hp0 = {h0, h1}, hp1 = {h2, h3};
    __nv_bfloat162 lp0 = {__float2bfloat16_rn(v.x - __bfloat162float(h0)),
                          __float2bfloat16_rn(v.y - __bfloat162float(h1))};
    __nv_bfloat162 lp1 = {__float2bfloat16_rn(v.z - __bfloat162float(h2)),
                          __float2bfloat16_rn(v.w - __bfloat162float(h3))};
    uint2 hq = {*(uint32_t*)&hp0, *(uint32_t*)&hp1};
    uint2 lq = {*(uint32_t*)&lp0, *(uint32_t*)&lp1};
    *(uint2*)(g_hi + (size_t)idx * 4) = hq;
    *(uint2*)(g_lo + (size_t)idx * 4) = lq;
}

// ---------------- column max of pos_bias, phase 1 ------------------------------
__global__ void colmax_part_kernel(const float* __restrict__ pb) {
    int c  = blockIdx.x * 256 + threadIdx.x;
    int r0 = blockIdx.y * 64;
    float m = -3.402823e38f;
#pragma unroll 4
    for (int r = 0; r < 64; ++r)
        m = fmaxf(m, pb[(size_t)(r0 + r) * T_LEN + c]);
    g_colmax_part[blockIdx.y * T_LEN + c] = m;
}

// ---------------- phase 2 merged with expw2 ------------------------------------
__global__ void colmax_expw_kernel(const float* __restrict__ pb) {
    if (blockIdx.x < 8) {
        int c = blockIdx.x * 256 + threadIdx.x;
        float m = -3.402823e38f;
#pragma unroll
        for (int i = 0; i < 32; ++i)
            m = fmaxf(m, g_colmax_part[i * T_LEN + c]);
        g_pbmax[c] = fmaxf(m, 0.0f);                 // relu folded
    } else {
        int i = (blockIdx.x - 8) * 256 + threadIdx.x;  // 0..65535
        int t = i >> 5;
        int j = i & 31;
        int idx = t - SWIN + 1 + j;
        float w = (idx >= 0) ? __expf(pb[(size_t)t * T_LEN + idx]) : 0.0f;
        g_expw2[i] = make_float2(w, w);
    }
}

// ---------------- max_logit[d] = max_t ( k[t,0,d] + relu(pbmax[t]) ) ----------
__global__ void ml_part_kernel() {
    int d  = blockIdx.x * 256 + threadIdx.x;     // 0..511
    int t0 = blockIdx.y * 16;
    float m0 = -3.402823e38f, m1 = m0, m2 = m0, m3 = m0;
#pragma unroll
    for (int tt = 0; tt < 16; tt += 4) {
        int t = t0 + tt;
        m0 = fmaxf(m0, g_k[(size_t)(t + 0) * BDIM + d] + g_pbmax[t + 0]);
        m1 = fmaxf(m1, g_k[(size_t)(t + 1) * BDIM + d] + g_pbmax[t + 1]);
        m2 = fmaxf(m2, g_k[(size_t)(t + 2) * BDIM + d] + g_pbmax[t + 2]);
        m3 = fmaxf(m3, g_k[(size_t)(t + 3) * BDIM + d] + g_pbmax[t + 3]);
    }
    g_ml_part[blockIdx.y * DMODEL + d] = fmaxf(fmaxf(m0, m1), fmaxf(m2, m3));
}

__global__ void ml_comb_kernel() {
    int d = blockIdx.x * 256 + threadIdx.x;
    float m = -3.402823e38f;
#pragma unroll 8
    for (int i = 0; i < 128; ++i) m = fmaxf(m, g_ml_part[i * DMODEL + d]);
    g_ml[d] = m;
}

// ---------------- scan phase A: ek/ekv (packed) + per-chunk sums ---------------
__global__ void scan_partial_kernel() {
    int bd = blockIdx.x * 256 + threadIdx.x;
    int c  = blockIdx.y;
    float ml = g_ml[bd & (DMODEL - 1)];
    float sd = 0.0f, sn = 0.0f;
    size_t base = (size_t)c * 32 * BDIM + bd;
#pragma unroll 8
    for (int i = 0; i < 32; ++i) {
        size_t off = base + (size_t)i * BDIM;
        float e  = __expf(g_k[off] - ml);
        float ev = e * g_v[off];
        g_ekk[off] = make_float2(e, ev);
        sd += e;
        sn += ev;
    }
    g_ps2[c * BDIM + bd] = make_float2(sd, sn);
}

// ---------------- scan phase B: exclusive prefix over 64 chunks (MLP 16) -------
__global__ void scan_prefix_kernel() {
    int bd = blockIdx.x * 256 + threadIdx.x;     // 0..1023
    float sx = 0.0f, sy = 0.0f;
    for (int cb = 0; cb < NCHUNK; cb += 16) {
        float2 v[16];
#pragma unroll
        for (int j = 0; j < 16; ++j) v[j] = g_ps2[(cb + j) * BDIM + bd];
#pragma unroll
        for (int j = 0; j < 16; ++j) {
            float2 t = v[j];
            g_ps2[(cb + j) * BDIM + bd] = make_float2(sx, sy);
            sx += t.x;
            sy += t.y;
        }
    }
}

// ---------------- fused window + cumsum + combine; emits y as bf16 hi/lo -------
__global__ void __launch_bounds__(256) aft_fused_kernel() {
    __shared__ float2 w2s[32 * SWIN];
    const int tid = threadIdx.x;
    const int bd  = blockIdx.x * 256 + tid;
    const int c   = blockIdx.y;
    const int t0  = c * 32;

#pragma unroll
    for (int it = 0; it < 4; ++it) {
        int idx = it * 256 + tid;
        w2s[idx] = g_expw2[t0 * SWIN + idx];
    }
    __syncthreads();

    unsigned long long acc[32];
#pragma unroll
    for (int r = 0; r < 32; ++r) acc[r] = 0ULL;

    if (c > 0) {
        float2 ps = g_ps2[(c - 1) * BDIM + bd];
        unsigned long long cs2 = pack2(ps.x, ps.y);
#pragma unroll
        for (int i = 0; i < 32; ++i) {
            float2 e = g_ekk[(size_t)(t0 - 32 + i) * BDIM + bd];
            unsigned long long e2 = pack2(e.x, e.y);
            cs2 = add2(cs2, e2);
            acc[i] = add2(acc[i], cs2);
#pragma unroll
            for (int r = 0; r < 31; ++r) {
                if (r < i)
                    acc[r] = ffma2(*(const unsigned long long*)&w2s[r * 32 + (i - r - 1)],
                                   e2, acc[r]);
            }
        }
    }
#pragma unroll
    for (int i = 0; i < 32; ++i) {
        float2 e = g_ekk[(size_t)(t0 + i) * BDIM + bd];
        unsigned long long e2 = pack2(e.x, e.y);
#pragma unroll
        for (int r = 0; r < 32; ++r) {
            if (r >= i)
                acc[r] = ffma2(*(const unsigned long long*)&w2s[r * 32 + (i - r + 31)],
                               e2, acc[r]);
        }
    }

#pragma unroll
    for (int r = 0; r < 32; ++r) {
        float den, num;
        unpack2(acc[r], den, num);
        size_t off = (size_t)(t0 + r) * BDIM + bd;
        float q  = g_q[off];
        float sg = 1.0f / (1.0f + __expf(-q));
        float y  = sg * num / den;
        __nv_bfloat16 h = __float2bfloat16_rn(y);
        g_yh[off] = h;
        g_yl[off] = __float2bfloat16_rn(y - __bfloat162float(h));
    }
}

// ---------------- launch ------------------------------------------------------
extern "C" void kernel_launch(void* const* d_in, const int* in_sizes, int n_in,
                              void* d_out, int out_size) {
    const float* query = (const float*)d_in[0];
    const float* key   = (const float*)d_in[1];
    const float* value = (const float*)d_in[2];
    const float* Wq    = (const float*)d_in[3];
    const float* bq    = (const float*)d_in[4];
    const float* Wk    = (const float*)d_in[5];
    const float* bk    = (const float*)d_in[6];
    const float* Wv    = (const float*)d_in[7];
    const float* bv    = (const float*)d_in[8];
    const float* pb    = (const float*)d_in[9];
    const float* Wo    = (const float*)d_in[10];
    const float* bo    = (const float*)d_in[11];
    float* out = (float*)d_out;

    cudaFuncSetAttribute(gemm_qkv_kernel,
                         cudaFuncAttributeMaxDynamicSharedMemorySize, SMEM_MMA);
    cudaFuncSetAttribute(gemm_o_kernel,
                         cudaFuncAttributeMaxDynamicSharedMemorySize, SMEM_MMA);

    cvt_kernel<<<(TOT_F4 + 255) / 256, 256>>>(query, key, value, Wq, Wk, Wv, Wo);

    colmax_part_kernel<<<dim3(8, 32), 256>>>(pb);
    colmax_expw_kernel<<<8 + 256, 256>>>(pb);

    gemm_qkv_kernel<<<dim3(4, 32, 3), 256, SMEM_MMA>>>(bq, bk, bv);

    ml_part_kernel<<<dim3(2, 128), 256>>>();
    ml_comb_kernel<<<2, 256>>>();

    scan_partial_kernel<<<dim3(4, 64), 256>>>();
    scan_prefix_kernel<<<4, 256>>>();

    aft_fused_kernel<<<dim3(4, 64), 256>>>();

    gemm_o_kernel<<<dim3(4, 32), 256, SMEM_MMA>>>(bo, out);
}

// round 11
// speedup vs baseline: 1.0754x; 1.0754x over previous
#include <cuda_runtime.h>
#include <cuda_bf16.h>
#include <cstdint>

#define T_LEN  2048
#define NBATCH 2
#define DMODEL 512
#define SWIN   32
#define MROWS  4096      // T_LEN * NBATCH
#define BDIM   1024      // NBATCH * DMODEL
#define NCHUNK 64        // T_LEN / 32

// bf16 hi/lo pool layout (element offsets)
#define IN_ELEMS   (MROWS * DMODEL)          // 2097152
#define W_ELEMS    (DMODEL * DMODEL)         // 262144
#define OFF_XQ     0
#define OFF_XK     (IN_ELEMS)
#define OFF_XV     (2 * IN_ELEMS)
#define OFF_WQ     (3 * IN_ELEMS)
#define OFF_WK     (3 * IN_ELEMS + W_ELEMS)
#define OFF_WV     (3 * IN_ELEMS + 2 * W_ELEMS)
#define OFF_WO     (3 * IN_ELEMS + 3 * W_ELEMS)
#define TOT_ELEMS  (3 * IN_ELEMS + 4 * W_ELEMS)   // 7340032
#define IN_F4      (IN_ELEMS / 4)
#define W_F4       (W_ELEMS / 4)
#define TOT_F4     (TOT_ELEMS / 4)                // 1835008

// ---------------- device scratch ----------------------------------------------
__device__ float  g_q  [MROWS * DMODEL];
__device__ float  g_k  [MROWS * DMODEL];
__device__ float  g_v  [MROWS * DMODEL];
__device__ __nv_bfloat16 g_hi[TOT_ELEMS];
__device__ __nv_bfloat16 g_lo[TOT_ELEMS];
__device__ __nv_bfloat16 g_yh[MROWS * DMODEL];
__device__ __nv_bfloat16 g_yl[MROWS * DMODEL];
__device__ float2 g_ekk[T_LEN * BDIM];          // (ek, ek*v) packed
__device__ float2 g_ps2[NCHUNK * BDIM];         // chunk partials -> exclusive prefix
__device__ float  g_colmax_part[32 * T_LEN];
__device__ float  g_pbmax[T_LEN];
__device__ float  g_ml_part[128 * DMODEL];
__device__ float  g_ml[DMODEL];
__device__ float2 g_expw2[T_LEN * SWIN];        // (w, w) duplicated weights

// ---------------- packed f32x2 helpers ----------------------------------------
__device__ __forceinline__ unsigned long long pack2(float lo, float hi) {
    unsigned long long r;
    asm("mov.b64 %0, {%1, %2};" : "=l"(r) : "f"(lo), "f"(hi));
    return r;
}
__device__ __forceinline__ void unpack2(unsigned long long v, float& lo, float& hi) {
    asm("mov.b64 {%0, %1}, %2;" : "=f"(lo), "=f"(hi) : "l"(v));
}
__device__ __forceinline__ unsigned long long ffma2(unsigned long long a,
                                                    unsigned long long b,
                                                    unsigned long long c) {
    unsigned long long d;
    asm("fma.rn.f32x2 %0, %1, %2, %3;" : "=l"(d) : "l"(a), "l"(b), "l"(c));
    return d;
}
__device__ __forceinline__ unsigned long long add2(unsigned long long a,
                                                   unsigned long long b) {
    unsigned long long d;
    asm("add.rn.f32x2 %0, %1, %2;" : "=l"(d) : "l"(a), "l"(b));
    return d;
}

// ================= bf16x3 split-precision warp-MMA GEMM ========================
#define LDT     40                       // bf16 elems per smem row (32 + 8 pad)
#define TILE_BYTES (128 * LDT * 2)       // 10240 B
#define STAGE_BYTES (4 * TILE_BYTES)     // Ah, Al, Bh, Bl = 40960 B
#define NSTAGE  2
#define SMEM_MMA (NSTAGE * STAGE_BYTES)  // 81920 B -> 2 CTAs/SM

__device__ __forceinline__ uint32_t smem_u32(const void* p) {
    uint32_t a;
    asm("{ .reg .u64 t; cvta.to.shared.u64 t, %1; cvt.u32.u64 %0, t; }"
        : "=r"(a) : "l"(p));
    return a;
}
__device__ __forceinline__ void cpa16(uint32_t dst, const void* src) {
    asm volatile("cp.async.ca.shared.global [%0], [%1], 16;"
                 :: "r"(dst), "l"(src));
}
#define CP_COMMIT() asm volatile("cp.async.commit_group;" ::: "memory")
#define CP_WAIT(n)  asm volatile("cp.async.wait_group %0;" :: "n"(n) : "memory")

__device__ __forceinline__ void ldsm4(uint32_t* r, uint32_t a) {
    asm volatile("ldmatrix.sync.aligned.m8n8.x4.shared.b16 {%0,%1,%2,%3}, [%4];"
                 : "=r"(r[0]), "=r"(r[1]), "=r"(r[2]), "=r"(r[3]) : "r"(a));
}
__device__ __forceinline__ void mma_bf16(float* c, const uint32_t* a, const uint32_t* b) {
    asm volatile(
        "mma.sync.aligned.m16n8k16.row.col.f32.bf16.bf16.f32 "
        "{%0,%1,%2,%3}, {%4,%5,%6,%7}, {%8,%9}, {%0,%1,%2,%3};"
        : "+f"(c[0]), "+f"(c[1]), "+f"(c[2]), "+f"(c[3])
        : "r"(a[0]), "r"(a[1]), "r"(a[2]), "r"(a[3]), "r"(b[0]), "r"(b[1]));
}

// A/B already split to bf16 hi/lo in gmem; mainloop = cp.async + ldmatrix + MMA.
// 2-stage pipeline, ONE __syncthreads per chunk: wait -> sync -> issue c+1 -> compute c.
__device__ __forceinline__ void gemm_mma_body(const __nv_bfloat16* __restrict__ Ah,
                                              const __nv_bfloat16* __restrict__ Al,
                                              const __nv_bfloat16* __restrict__ Bh,
                                              const __nv_bfloat16* __restrict__ Bl,
                                              const float* __restrict__ bias,
                                              float* __restrict__ out) {
    extern __shared__ char smem[];
    const int tid    = threadIdx.x;
    const int lane   = tid & 31;
    const int wid    = tid >> 5;
    const int warp_m = wid & 1;
    const int warp_n = wid >> 1;
    const int m0 = blockIdx.y * 128;
    const int n0 = blockIdx.x * 128;

    const uint32_t sbase = smem_u32(smem);
    const uint32_t a_off = ((warp_m * 64 + (lane & 15)) * LDT + ((lane >> 4) * 8)) * 2;
    const uint32_t b_off = ((warp_n * 32 + (lane & 7) + ((lane >> 4) & 1) * 8) * LDT
                            + (((lane >> 3) & 1) * 8)) * 2;

    const __nv_bfloat16* srcs[4] = {Ah + (size_t)m0 * 512, Al + (size_t)m0 * 512,
                                    Bh + (size_t)n0 * 512, Bl + (size_t)n0 * 512};

    float acc[4][4][4];
#pragma unroll
    for (int i = 0; i < 4; ++i)
#pragma unroll
        for (int j = 0; j < 4; ++j)
#pragma unroll
            for (int q = 0; q < 4; ++q) acc[i][j][q] = 0.0f;

    auto issue_stage = [&](int c) {
        const uint32_t sb = sbase + (c & 1) * STAGE_BYTES;
#pragma unroll
        for (int i = 0; i < 8; ++i) {
            int q   = i * 256 + tid;
            int tile = q >> 9;           // constant per unrolled i
            int s    = q & 511;
            int row  = s >> 2, ch = s & 3;
            const __nv_bfloat16* src = srcs[tile] + (size_t)row * 512 + c * 32 + ch * 8;
            cpa16(sb + tile * TILE_BYTES + row * (LDT * 2) + ch * 16, src);
        }
        CP_COMMIT();
    };

    issue_stage(0);

    for (int c = 0; c < 16; ++c) {
        CP_WAIT(0);
        __syncthreads();                 // stage c ready; all warps done with c-1
        if (c + 1 < 16) issue_stage(c + 1);   // overlaps compute below

        const uint32_t sa = sbase + (c & 1) * STAGE_BYTES;

#pragma unroll
        for (int kf = 0; kf < 2; ++kf) {
            const uint32_t kb = kf * 32;    // 16 bf16 = 32 bytes
            uint32_t bh4[2][4], bl4[2][4];
#pragma unroll
            for (int p = 0; p < 2; ++p) {
                uint32_t ba = sa + 2 * TILE_BYTES + b_off + p * (16 * LDT * 2) + kb;
                ldsm4(bh4[p], ba);
                ldsm4(bl4[p], ba + TILE_BYTES);
            }
#pragma unroll
            for (int mf = 0; mf < 4; ++mf) {
                uint32_t aa = sa + a_off + mf * (16 * LDT * 2) + kb;
                uint32_t ah[4], al[4];
                ldsm4(ah, aa);
                ldsm4(al, aa + TILE_BYTES);
#pragma unroll
                for (int nf = 0; nf < 4; ++nf) {
                    const uint32_t* bh = &bh4[nf >> 1][(nf & 1) * 2];
                    const uint32_t* bl = &bl4[nf >> 1][(nf & 1) * 2];
                    mma_bf16(acc[mf][nf], ah, bh);
                    mma_bf16(acc[mf][nf], ah, bl);
                    mma_bf16(acc[mf][nf], al, bh);
                }
            }
        }
    }

    const int rbase = m0 + warp_m * 64 + (lane >> 2);
    const int cbase = n0 + warp_n * 32 + (lane & 3) * 2;
#pragma unroll
    for (int mf = 0; mf < 4; ++mf) {
#pragma unroll
        for (int nf = 0; nf < 4; ++nf) {
            int col = cbase + nf * 8;
            float b0 = bias[col], b1 = bias[col + 1];
            float* p0 = out + (size_t)(rbase + mf * 16) * 512 + col;
            float* p1 = p0 + 8 * 512;
            float2 v0 = {acc[mf][nf][0] + b0, acc[mf][nf][1] + b1};
            float2 v1 = {acc[mf][nf][2] + b0, acc[mf][nf][3] + b1};
            *(float2*)p0 = v0;
            *(float2*)p1 = v1;
        }
    }
}

__global__ void __launch_bounds__(256, 2)
gemm_qkv_kernel(const float* __restrict__ bq, const float* __restrict__ bk,
                const float* __restrict__ bv) {
    if (blockIdx.z == 0)
        gemm_mma_body(g_hi + OFF_XQ, g_lo + OFF_XQ, g_hi + OFF_WQ, g_lo + OFF_WQ, bq, g_q);
    else if (blockIdx.z == 1)
        gemm_mma_body(g_hi + OFF_XK, g_lo + OFF_XK, g_hi + OFF_WK, g_lo + OFF_WK, bk, g_k);
    else
        gemm_mma_body(g_hi + OFF_XV, g_lo + OFF_XV, g_hi + OFF_WV, g_lo + OFF_WV, bv, g_v);
}

__global__ void __launch_bounds__(256, 2)
gemm_o_kernel(const float* __restrict__ bo, float* __restrict__ out) {
    gemm_mma_body(g_yh, g_yl, g_hi + OFF_WO, g_lo + OFF_WO, bo, out);
}

// ---------------- fp32 -> bf16 hi/lo split, one pass over X(q,k,v) + W --------
__global__ void cvt_kernel(const float* __restrict__ xq, const float* __restrict__ xk,
                           const float* __restrict__ xv, const float* __restrict__ Wq,
                           const float* __restrict__ Wk, const float* __restrict__ Wv,
                           const float* __restrict__ Wo) {
    int idx = blockIdx.x * 256 + threadIdx.x;      // float4 index
    if (idx >= TOT_F4) return;
    const float* src;
    int local;
    if (idx < 3 * IN_F4) {
        int w = idx / IN_F4;
        src = (w == 0) ? xq : (w == 1) ? xk : xv;
        local = idx - w * IN_F4;
    } else {
        int r = idx - 3 * IN_F4;
        int w = r / W_F4;
        src = (w == 0) ? Wq : (w == 1) ? Wk : (w == 2) ? Wv : Wo;
        local = r - w * W_F4;
    }
    float4 v = ((const float4*)src)[local];
    __nv_bfloat16 h0 = __float2bfloat16_rn(v.x);
    __nv_bfloat16 h1 = __float2bfloat16_rn(v.y);
    __nv_bfloat16 h2 = __float2bfloat16_rn(v.z);
    __nv_bfloat16 h3 = __float2bfloat16_rn(v.w);
    __nv_bfloat162 hp0 = {h0, h1}, hp1 = {h2, h3};
    __nv_bfloat162 lp0 = {__float2bfloat16_rn(v.x - __bfloat162float(h0)),
                          __float2bfloat16_rn(v.y - __bfloat162float(h1))};
    __nv_bfloat162 lp1 = {__float2bfloat16_rn(v.z - __bfloat162float(h2)),
                          __float2bfloat16_rn(v.w - __bfloat162float(h3))};
    uint2 hq = {*(uint32_t*)&hp0, *(uint32_t*)&hp1};
    uint2 lq = {*(uint32_t*)&lp0, *(uint32_t*)&lp1};
    *(uint2*)(g_hi + (size_t)idx * 4) = hq;
    *(uint2*)(g_lo + (size_t)idx * 4) = lq;
}

// ---------------- column max of pos_bias, phase 1 ------------------------------
__global__ void colmax_part_kernel(const float* __restrict__ pb) {
    int c  = blockIdx.x * 256 + threadIdx.x;
    int r0 = blockIdx.y * 64;
    float m = -3.402823e38f;
#pragma unroll 4
    for (int r = 0; r < 64; ++r)
        m = fmaxf(m, pb[(size_t)(r0 + r) * T_LEN + c]);
    g_colmax_part[blockIdx.y * T_LEN + c] = m;
}

// ---------------- phase 2 merged with expw2 ------------------------------------
__global__ void colmax_expw_kernel(const float* __restrict__ pb) {
    if (blockIdx.x < 8) {
        int c = blockIdx.x * 256 + threadIdx.x;
        float m = -3.402823e38f;
#pragma unroll
        for (int i = 0; i < 32; ++i)
            m = fmaxf(m, g_colmax_part[i * T_LEN + c]);
        g_pbmax[c] = fmaxf(m, 0.0f);                 // relu folded
    } else {
        int i = (blockIdx.x - 8) * 256 + threadIdx.x;  // 0..65535
        int t = i >> 5;
        int j = i & 31;
        int idx = t - SWIN + 1 + j;
        float w = (idx >= 0) ? __expf(pb[(size_t)t * T_LEN + idx]) : 0.0f;
        g_expw2[i] = make_float2(w, w);
    }
}

// ---------------- max_logit[d] = max_t ( k[t,0,d] + relu(pbmax[t]) ) ----------
__global__ void ml_part_kernel() {
    int d  = blockIdx.x * 256 + threadIdx.x;     // 0..511
    int t0 = blockIdx.y * 16;
    float m0 = -3.402823e38f, m1 = m0, m2 = m0, m3 = m0;
#pragma unroll
    for (int tt = 0; tt < 16; tt += 4) {
        int t = t0 + tt;
        m0 = fmaxf(m0, g_k[(size_t)(t + 0) * BDIM + d] + g_pbmax[t + 0]);
        m1 = fmaxf(m1, g_k[(size_t)(t + 1) * BDIM + d] + g_pbmax[t + 1]);
        m2 = fmaxf(m2, g_k[(size_t)(t + 2) * BDIM + d] + g_pbmax[t + 2]);
        m3 = fmaxf(m3, g_k[(size_t)(t + 3) * BDIM + d] + g_pbmax[t + 3]);
    }
    g_ml_part[blockIdx.y * DMODEL + d] = fmaxf(fmaxf(m0, m1), fmaxf(m2, m3));
}

__global__ void ml_comb_kernel() {
    int d = blockIdx.x * 256 + threadIdx.x;
    float m = -3.402823e38f;
#pragma unroll 8
    for (int i = 0; i < 128; ++i) m = fmaxf(m, g_ml_part[i * DMODEL + d]);
    g_ml[d] = m;
}

// ---------------- scan phase A: ek/ekv (packed) + per-chunk sums ---------------
__global__ void scan_partial_kernel() {
    int bd = blockIdx.x * 256 + threadIdx.x;
    int c  = blockIdx.y;
    float ml = g_ml[bd & (DMODEL - 1)];
    float sd = 0.0f, sn = 0.0f;
    size_t base = (size_t)c * 32 * BDIM + bd;
#pragma unroll 8
    for (int i = 0; i < 32; ++i) {
        size_t off = base + (size_t)i * BDIM;
        float e  = __expf(g_k[off] - ml);
        float ev = e * g_v[off];
        g_ekk[off] = make_float2(e, ev);
        sd += e;
        sn += ev;
    }
    g_ps2[c * BDIM + bd] = make_float2(sd, sn);
}

// ---------------- scan phase B: exclusive prefix over 64 chunks (MLP 16) -------
__global__ void scan_prefix_kernel() {
    int bd = blockIdx.x * 256 + threadIdx.x;     // 0..1023
    float sx = 0.0f, sy = 0.0f;
    for (int cb = 0; cb < NCHUNK; cb += 16) {
        float2 v[16];
#pragma unroll
        for (int j = 0; j < 16; ++j) v[j] = g_ps2[(cb + j) * BDIM + bd];
#pragma unroll
        for (int j = 0; j < 16; ++j) {
            float2 t = v[j];
            g_ps2[(cb + j) * BDIM + bd] = make_float2(sx, sy);
            sx += t.x;
            sy += t.y;
        }
    }
}

// ---------------- fused window + cumsum + combine; emits y as bf16 hi/lo -------
__global__ void __launch_bounds__(256) aft_fused_kernel() {
    __shared__ float2 w2s[32 * SWIN];
    const int tid = threadIdx.x;
    const int bd  = blockIdx.x * 256 + tid;
    const int c   = blockIdx.y;
    const int t0  = c * 32;

#pragma unroll
    for (int it = 0; it < 4; ++it) {
        int idx = it * 256 + tid;
        w2s[idx] = g_expw2[t0 * SWIN + idx];
    }
    __syncthreads();

    unsigned long long acc[32];
#pragma unroll
    for (int r = 0; r < 32; ++r) acc[r] = 0ULL;

    if (c > 0) {
        float2 ps = g_ps2[(c - 1) * BDIM + bd];
        unsigned long long cs2 = pack2(ps.x, ps.y);
#pragma unroll
        for (int i = 0; i < 32; ++i) {
            float2 e = g_ekk[(size_t)(t0 - 32 + i) * BDIM + bd];
            unsigned long long e2 = pack2(e.x, e.y);
            cs2 = add2(cs2, e2);
            acc[i] = add2(acc[i], cs2);
#pragma unroll
            for (int r = 0; r < 31; ++r) {
                if (r < i)
                    acc[r] = ffma2(*(const unsigned long long*)&w2s[r * 32 + (i - r - 1)],
                                   e2, acc[r]);
            }
        }
    }
#pragma unroll
    for (int i = 0; i < 32; ++i) {
        float2 e = g_ekk[(size_t)(t0 + i) * BDIM + bd];
        unsigned long long e2 = pack2(e.x, e.y);
#pragma unroll
        for (int r = 0; r < 32; ++r) {
            if (r >= i)
                acc[r] = ffma2(*(const unsigned long long*)&w2s[r * 32 + (i - r + 31)],
                               e2, acc[r]);
        }
    }

#pragma unroll
    for (int r = 0; r < 32; ++r) {
        float den, num;
        unpack2(acc[r], den, num);
        size_t off = (size_t)(t0 + r) * BDIM + bd;
        float q  = g_q[off];
        float sg = 1.0f / (1.0f + __expf(-q));
        float y  = sg * num / den;
        __nv_bfloat16 h = __float2bfloat16_rn(y);
        g_yh[off] = h;
        g_yl[off] = __float2bfloat16_rn(y - __bfloat162float(h));
    }
}

// ---------------- launch ------------------------------------------------------
extern "C" void kernel_launch(void* const* d_in, const int* in_sizes, int n_in,
                              void* d_out, int out_size) {
    const float* query = (const float*)d_in[0];
    const float* key   = (const float*)d_in[1];
    const float* value = (const float*)d_in[2];
    const float* Wq    = (const float*)d_in[3];
    const float* bq    = (const float*)d_in[4];
    const float* Wk    = (const float*)d_in[5];
    const float* bk    = (const float*)d_in[6];
    const float* Wv    = (const float*)d_in[7];
    const float* bv    = (const float*)d_in[8];
    const float* pb    = (const float*)d_in[9];
    const float* Wo    = (const float*)d_in[10];
    const float* bo    = (const float*)d_in[11];
    float* out = (float*)d_out;

    cudaFuncSetAttribute(gemm_qkv_kernel,
                         cudaFuncAttributeMaxDynamicSharedMemorySize, SMEM_MMA);
    cudaFuncSetAttribute(gemm_o_kernel,
                         cudaFuncAttributeMaxDynamicSharedMemorySize, SMEM_MMA);

    cvt_kernel<<<(TOT_F4 + 255) / 256, 256>>>(query, key, value, Wq, Wk, Wv, Wo);

    colmax_part_kernel<<<dim3(8, 32), 256>>>(pb);
    colmax_expw_kernel<<<8 + 256, 256>>>(pb);

    gemm_qkv_kernel<<<dim3(4, 32, 3), 256, SMEM_MMA>>>(bq, bk, bv);

    ml_part_kernel<<<dim3(2, 128), 256>>>();
    ml_comb_kernel<<<2, 256>>>();

    scan_partial_kernel<<<dim3(4, 64), 256>>>();
    scan_prefix_kernel<<<4, 256>>>();

    aft_fused_kernel<<<dim3(4, 64), 256>>>();

    gemm_o_kernel<<<dim3(4, 32), 256, SMEM_MMA>>>(bo, out);
}